// round 8
// baseline (speedup 1.0000x reference)
#include <cuda_runtime.h>
#include <cuda_bf16.h>
#include <math.h>
#include <stdint.h>

#define GN 3136          // H*W
#define CC 384
#define BB 8
#define NHEADS 8
#define HD 48
#define SZ (BB*CC*GN)    // 9,633,792

typedef __nv_bfloat16 bf16;
typedef __nv_bfloat162 bf162;

// ---------------- scratch (static device globals; no runtime alloc) ----------------
__device__ __align__(16) float g_bufA[SZ];       // conv mid (fp32, dwconv input)
__device__ __align__(16) float g_x1b[SZ];        // x1 fp32
__device__ __align__(16) float g_x2b[SZ];        // x2 fp32
__device__ __align__(16) float g_qkvb[3*SZ];     // qkv fp32
__device__ __align__(16) float g_w1f[CC*CC];
__device__ __align__(16) float g_b1f[CC];
__device__ __align__(16) float g_dwf[CC*9];
__device__ __align__(16) float g_dbf[CC];
__device__ __align__(16) float g_w1t[CC*4*CC];
__device__ __align__(16) float g_w2t[CC*4*CC];
__device__ __align__(16) float g_kv[BB*NHEADS*HD*HD];
__device__ __align__(16) float g_ksum[BB*NHEADS*HD];

// bf16 hi/lo activation buffers
__device__ __align__(16) bf16 g_xh[SZ],   g_xl[SZ];
__device__ __align__(16) bf16 g_dwh[SZ],  g_dwl[SZ];
__device__ __align__(16) bf16 g_x1h[SZ],  g_x1l[SZ];
__device__ __align__(16) bf16 g_aoh[SZ],  g_aol[SZ];
__device__ __align__(16) bf16 g_lnh[SZ],  g_lnl[SZ];
__device__ __align__(16) bf16 g_hmh[4*SZ], g_hml[4*SZ];
// bf16 hi/lo weights
__device__ __align__(16) bf16 g_w1fh[CC*CC],   g_w1fl[CC*CC];
__device__ __align__(16) bf16 g_cw2h[CC*CC],   g_cw2l[CC*CC];
__device__ __align__(16) bf16 g_qkvh[3*CC*CC], g_qkvl[3*CC*CC];
__device__ __align__(16) bf16 g_projh[CC*CC],  g_projl[CC*CC];
__device__ __align__(16) bf16 g_w1th[CC*4*CC], g_w1tl[CC*4*CC];
__device__ __align__(16) bf16 g_w2th[CC*4*CC], g_w2tl[CC*4*CC];

// ---------------- helpers ----------------
__device__ __forceinline__ void split2(float x, bf16& h, bf16& l) {
    h = __float2bfloat16(x);
    l = __float2bfloat16(x - __bfloat162float(h));
}

__device__ __forceinline__ void ldsm4(uint32_t* r, uint32_t a) {
    asm volatile("ldmatrix.sync.aligned.m8n8.x4.shared.b16 {%0,%1,%2,%3}, [%4];"
                 : "=r"(r[0]), "=r"(r[1]), "=r"(r[2]), "=r"(r[3]) : "r"(a));
}
__device__ __forceinline__ void ldsm4t(uint32_t* r, uint32_t a) {
    asm volatile("ldmatrix.sync.aligned.m8n8.x4.trans.shared.b16 {%0,%1,%2,%3}, [%4];"
                 : "=r"(r[0]), "=r"(r[1]), "=r"(r[2]), "=r"(r[3]) : "r"(a));
}
__device__ __forceinline__ void mma16816(float* c, const uint32_t* a, const uint32_t* b) {
    asm volatile("mma.sync.aligned.m16n8k16.row.col.f32.bf16.bf16.f32 "
                 "{%0,%1,%2,%3}, {%4,%5,%6,%7}, {%8,%9}, {%0,%1,%2,%3};"
                 : "+f"(c[0]), "+f"(c[1]), "+f"(c[2]), "+f"(c[3])
                 : "r"(a[0]), "r"(a[1]), "r"(a[2]), "r"(a[3]), "r"(b[0]), "r"(b[1]));
}
__device__ __forceinline__ void cpa16(uint32_t dst, const void* src) {
    asm volatile("cp.async.ca.shared.global [%0], [%1], 16;" :: "r"(dst), "l"(src));
}

// ---------------- BN folding ----------------
__global__ void fold_bn1_kernel(const float* __restrict__ cw1, const float* __restrict__ cb1,
                                const float* __restrict__ w, const float* __restrict__ bvec,
                                const float* __restrict__ m, const float* __restrict__ v) {
    int o = blockIdx.x;
    int tid = threadIdx.x;   // 128
    float part = 0.f;
    for (int i = tid; i < CC; i += 128) {
        float s = w[i] * rsqrtf(v[i] + 1e-5f);
        float t = bvec[i] - m[i] * s;
        float cv = cw1[o*CC + i];
        g_w1f[o*CC + i] = cv * s;
        part += cv * t;
    }
    __shared__ float red[128];
    red[tid] = part; __syncthreads();
    for (int st = 64; st > 0; st >>= 1) { if (tid < st) red[tid] += red[tid+st]; __syncthreads(); }
    if (tid == 0) g_b1f[o] = cb1[o] + red[0];
}

__global__ void fold_bn2_kernel(const float* __restrict__ dw, const float* __restrict__ db,
                                const float* __restrict__ w, const float* __restrict__ bvec,
                                const float* __restrict__ m, const float* __restrict__ v) {
    int c = blockIdx.x * blockDim.x + threadIdx.x;
    if (c < CC) {
        float s = w[c] * rsqrtf(v[c] + 1e-5f);
        float t = bvec[c] - m[c] * s;
        #pragma unroll
        for (int k = 0; k < 9; k++) g_dwf[c*9 + k] = dw[c*9 + k] * s;
        g_dbf[c] = db[c] * s + t;
    }
}

__global__ void transpose_kernel(const float* __restrict__ src, float* __restrict__ dst,
                                 int srows, int scols) {
    int idx = blockIdx.x * 256 + threadIdx.x;
    if (idx < srows * scols) {
        int a = idx / srows;
        int b = idx - a * srows;
        dst[idx] = src[b * scols + a];
    }
}

__global__ void split_kernel(const float* __restrict__ src, bf16* __restrict__ h,
                             bf16* __restrict__ l, int n) {
    int i = blockIdx.x * 256 + threadIdx.x;
    if (i < n) {
        bf16 hh, ll;
        split2(src[i], hh, ll);
        h[i] = hh; l[i] = ll;
    }
}

__global__ void zero_kv_kernel() {
    int i = blockIdx.x * 256 + threadIdx.x;
    if (i < BB*NHEADS*HD*HD) g_kv[i] = 0.f;
    if (i < BB*NHEADS*HD)    g_ksum[i] = 0.f;
}

// ---------------- bf16 split GEMM (tensor core, mma.sync) ----------------
// Y[b,o,n] = act(W[o,:]·X[b,:,n] + bias[o]) (+ res), W = Wh+Wl, X = Xh+Xl (bf16 split)
// BM=128, BN=128, BK=32, 256 threads, 8 warps (2m x 4n), warp tile 64x32.
// smem/stage: A (hi|lo per 128B row, 128 rows) 16KB; B hi 2 nblk x 32k x 128B = 8KB; B lo 8KB.
#define SM_A    0
#define SM_BH   16384
#define SM_BL   24576
#define SM_BUF  32768
#define SMEM_DYN (2*SM_BUF)

template<int ACT>
__global__ __launch_bounds__(256)
void gemm_bf16(const bf16* __restrict__ Wh, const bf16* __restrict__ Wl,
               const bf16* __restrict__ Xh, const bf16* __restrict__ Xl,
               const float* __restrict__ bias, const float* __restrict__ res,
               float* __restrict__ YF, bf16* __restrict__ YH, bf16* __restrict__ YL,
               int Cout, int K) {
    const int b  = blockIdx.z;
    const int m0 = blockIdx.y * 128;
    const int n0 = blockIdx.x * 128;
    const bf16* Xhb = Xh + (size_t)b * K * GN;
    const bf16* Xlb = Xl + (size_t)b * K * GN;
    const size_t obase = (size_t)b * Cout * GN;

    extern __shared__ __align__(16) unsigned char smraw[];
    const uint32_t smbase = (uint32_t)__cvta_generic_to_shared(smraw);

    const int tid  = threadIdx.x;
    const int lane = tid & 31;
    const int wid  = tid >> 5;
    const int warp_m = wid & 1;        // 2
    const int warp_n = wid >> 1;       // 4
    const int m_base = warp_m * 64;
    const int n_base = warp_n * 32;

    const int r8   = (lane & 7) + ((lane >> 3) & 1) * 8;  // ldmatrix row-within-16
    const int cadd = lane >> 4;                            // ldmatrix chunk add (0/1)

    float acc[4][4][4];
    #pragma unroll
    for (int i = 0; i < 4; i++)
        #pragma unroll
        for (int nt = 0; nt < 4; nt++)
            #pragma unroll
            for (int q = 0; q < 4; q++) acc[i][nt][q] = 0.f;

    // copy coords
    const int cpc = tid & 7;           // A chunk 0..7 (0-3 hi, 4-7 lo)
    const int cpm = tid >> 3;          // A base row 0..31
    const int cn  = tid & 15;          // B n-chunk 0..15 (8 n each)
    const int ck  = tid >> 4;          // B base k 0..15
    int nsrc = n0 + cn * 8;            // clamp for partial last n-block
    if (nsrc > GN - 8) nsrc = GN - 8;
    const int nb = cn >> 3, c2 = cn & 7;

    auto issue_tile = [&](int k0, int buf) {
        uint32_t sb = smbase + buf * SM_BUF;
        #pragma unroll
        for (int h = 0; h < 4; h++) {
            int m = cpm + 32*h;                          // 0..127
            uint32_t d = sb + SM_A + m*128 + ((cpc ^ (m & 7)) << 4);
            const bf16* s = (cpc < 4)
                ? (Wh + (size_t)(m0 + m) * K + k0 + cpc*8)
                : (Wl + (size_t)(m0 + m) * K + k0 + (cpc - 4)*8);
            cpa16(d, s);
        }
        #pragma unroll
        for (int h = 0; h < 2; h++) {
            int k = ck + 16*h;                           // 0..31
            uint32_t sw = (uint32_t)((c2 ^ (k & 7)) << 4);
            uint32_t doff = nb*4096 + k*128 + sw;
            cpa16(sb + SM_BH + doff, Xhb + (size_t)(k0 + k) * GN + nsrc);
            cpa16(sb + SM_BL + doff, Xlb + (size_t)(k0 + k) * GN + nsrc);
        }
        asm volatile("cp.async.commit_group;" ::: "memory");
    };

    issue_tile(0, 0);
    int cur = 0;
    const int nbw = warp_n >> 1;
    for (int k0 = 0; k0 < K; k0 += 32) {
        asm volatile("cp.async.wait_group 0;" ::: "memory");
        __syncthreads();
        if (k0 + 32 < K) issue_tile(k0 + 32, cur ^ 1);
        uint32_t sb = smbase + cur * SM_BUF;

        #pragma unroll
        for (int j = 0; j < 2; j++) {                    // two k16 steps
            uint32_t ah[4][4], al[4][4], bh[4][2], bl[4][2];
            #pragma unroll
            for (int i = 0; i < 4; i++) {
                int row = m_base + 16*i + r8;
                int ch = 2*j + cadd;                     // hi chunks 0..3
                ldsm4(ah[i], sb + SM_A + row*128 + ((ch ^ (row & 7)) << 4));
                int cl = 4 + 2*j + cadd;                 // lo chunks 4..7
                ldsm4(al[i], sb + SM_A + row*128 + ((cl ^ (row & 7)) << 4));
            }
            #pragma unroll
            for (int u = 0; u < 2; u++) {
                int rowk = 16*j + r8;
                int nc = (warp_n & 1)*4 + 2*u + cadd;    // within-block n chunk 0..7
                uint32_t boff = nbw*4096 + rowk*128 + ((nc ^ (rowk & 7)) << 4);
                uint32_t t[4];
                ldsm4t(t, sb + SM_BH + boff);
                bh[2*u][0] = t[0]; bh[2*u][1] = t[1];
                bh[2*u+1][0] = t[2]; bh[2*u+1][1] = t[3];
                ldsm4t(t, sb + SM_BL + boff);
                bl[2*u][0] = t[0]; bl[2*u][1] = t[1];
                bl[2*u+1][0] = t[2]; bl[2*u+1][1] = t[3];
            }
            #pragma unroll
            for (int i = 0; i < 4; i++)
                #pragma unroll
                for (int nt = 0; nt < 4; nt++) {
                    mma16816(acc[i][nt], ah[i], bh[nt]);
                    mma16816(acc[i][nt], ah[i], bl[nt]);
                    mma16816(acc[i][nt], al[i], bh[nt]);
                }
        }
        cur ^= 1;
        __syncthreads();
    }

    // epilogue
    const int g = lane >> 2, tc = lane & 3;
    #pragma unroll
    for (int i = 0; i < 4; i++) {
        #pragma unroll
        for (int half = 0; half < 2; half++) {
            int row = m0 + m_base + 16*i + g + 8*half;
            float bv = bias ? bias[row] : 0.f;
            size_t rowoff = obase + (size_t)row * GN;
            #pragma unroll
            for (int nt = 0; nt < 4; nt++) {
                int n = n0 + n_base + 8*nt + tc*2;
                if (n >= GN) continue;
                float v0 = acc[i][nt][2*half + 0] + bv;
                float v1 = acc[i][nt][2*half + 1] + bv;
                if (ACT == 1) {
                    v0 = 0.5f * v0 * (1.f + erff(v0 * 0.70710678118654752f));
                    v1 = 0.5f * v1 * (1.f + erff(v1 * 0.70710678118654752f));
                }
                if (res) {
                    float2 r = *reinterpret_cast<const float2*>(res + rowoff + n);
                    v0 += r.x; v1 += r.y;
                }
                if (YF) *reinterpret_cast<float2*>(YF + rowoff + n) = make_float2(v0, v1);
                if (YH) {
                    bf16 h0, l0, h1, l1;
                    split2(v0, h0, l0); split2(v1, h1, l1);
                    *reinterpret_cast<bf162*>(YH + rowoff + n) = __halves2bfloat162(h0, h1);
                    *reinterpret_cast<bf162*>(YL + rowoff + n) = __halves2bfloat162(l0, l1);
                }
            }
        }
    }
}

static void run_gemm(const bf16* Wh, const bf16* Wl, const bf16* Xh, const bf16* Xl,
                     const float* bias, const float* res,
                     float* YF, bf16* YH, bf16* YL, int Cout, int K, int act) {
    dim3 g((GN + 127)/128, Cout/128, BB), blk(256);
    if (act) {
        cudaFuncSetAttribute(gemm_bf16<1>, cudaFuncAttributeMaxDynamicSharedMemorySize, SMEM_DYN);
        gemm_bf16<1><<<g, blk, SMEM_DYN>>>(Wh, Wl, Xh, Xl, bias, res, YF, YH, YL, Cout, K);
    } else {
        cudaFuncSetAttribute(gemm_bf16<0>, cudaFuncAttributeMaxDynamicSharedMemorySize, SMEM_DYN);
        gemm_bf16<0><<<g, blk, SMEM_DYN>>>(Wh, Wl, Xh, Xl, bias, res, YF, YH, YL, Cout, K);
    }
}

// ---------------- depthwise 3x3 (BN2-folded), writes bf16 hi/lo ----------------
__global__ __launch_bounds__(256)
void dwconv_kernel(const float* __restrict__ in, bf16* __restrict__ oh, bf16* __restrict__ ol) {
    int bc = blockIdx.x;          // b*CC + c
    int c  = bc % CC;
    __shared__ float tile[58*58];
    const float* plane = in + (size_t)bc * GN;
    int tid = threadIdx.x;
    for (int idx = tid; idx < 58*58; idx += 256) {
        int ty = idx / 58, tx = idx - ty*58;
        int y = ty - 1, xq = tx - 1;
        float v = 0.f;
        if (y >= 0 && y < 56 && xq >= 0 && xq < 56) v = plane[y*56 + xq];
        tile[idx] = v;
    }
    __syncthreads();
    float w0=g_dwf[c*9+0], w1=g_dwf[c*9+1], w2=g_dwf[c*9+2];
    float w3=g_dwf[c*9+3], w4=g_dwf[c*9+4], w5=g_dwf[c*9+5];
    float w6=g_dwf[c*9+6], w7=g_dwf[c*9+7], w8=g_dwf[c*9+8];
    float bbv = g_dbf[c];
    bf16* ohp = oh + (size_t)bc * GN;
    bf16* olp = ol + (size_t)bc * GN;
    for (int p = tid; p < GN; p += 256) {
        int y = p / 56, xq = p - y*56;
        const float* t = &tile[y*58 + xq];
        float a = bbv + w0*t[0] + w1*t[1] + w2*t[2]
                      + w3*t[58] + w4*t[59] + w5*t[60]
                      + w6*t[116] + w7*t[117] + w8*t[118];
        bf16 hh, ll; split2(a, hh, ll);
        ohp[p] = hh; olp[p] = ll;
    }
}

// ---------------- linear attention ----------------
__device__ __forceinline__ float phi_f(float t) { return expf(0.5f * (2.f*t - t*t)); }

__global__ __launch_bounds__(256)
void attn_kv_kernel(const float* __restrict__ qkv) {
    int bh = blockIdx.x; int b = bh >> 3, hd = bh & 7;
    int n0 = blockIdx.y * 392;
    __shared__ float kp_s[28*48];
    __shared__ float vv_s[28*48];
    int tid = threadIdx.x;
    int dr[9], er[9];
    #pragma unroll
    for (int r = 0; r < 9; r++) { int de = tid + 256*r; dr[r] = de/48; er[r] = de - dr[r]*48; }
    float acc[9];
    #pragma unroll
    for (int r = 0; r < 9; r++) acc[r] = 0.f;
    float ks = 0.f;
    const float* kbase = qkv + ((size_t)(b*1152 + CC   + hd*HD)) * GN + n0;
    const float* vbase = qkv + ((size_t)(b*1152 + 2*CC + hd*HD)) * GN + n0;
    for (int j0 = 0; j0 < 392; j0 += 28) {
        for (int idx = tid; idx < 48*28; idx += 256) {
            int d = idx / 28, j = idx - d*28;
            float kvl = kbase[(size_t)d*GN + j0 + j];
            kp_s[j*48 + d] = phi_f(kvl);
            vv_s[j*48 + d] = vbase[(size_t)d*GN + j0 + j];
        }
        __syncthreads();
        #pragma unroll 4
        for (int j = 0; j < 28; j++) {
            #pragma unroll
            for (int r = 0; r < 9; r++)
                acc[r] = fmaf(kp_s[j*48 + dr[r]], vv_s[j*48 + er[r]], acc[r]);
        }
        if (tid < 48) {
            float s = 0.f;
            #pragma unroll 4
            for (int j = 0; j < 28; j++) s += kp_s[j*48 + tid];
            ks += s;
        }
        __syncthreads();
    }
    #pragma unroll
    for (int r = 0; r < 9; r++) atomicAdd(&g_kv[bh*2304 + tid + 256*r], acc[r]);
    if (tid < 48) atomicAdd(&g_ksum[bh*48 + tid], ks);
}

__global__ __launch_bounds__(256)
void attn_out_kernel(const float* __restrict__ qkv,
                     bf16* __restrict__ oh, bf16* __restrict__ ol) {
    int bh = blockIdx.x; int b = bh >> 3, hd = bh & 7;
    int n0 = blockIdx.y * 392;
    __shared__ float kv_s[2304];
    __shared__ float ks_s[48];
    __shared__ float qp_s[28*49];
    __shared__ float dinv[28];
    int tid = threadIdx.x;
    for (int i = tid; i < 2304; i += 256) kv_s[i] = g_kv[bh*2304 + i];
    if (tid < 48) ks_s[tid] = g_ksum[bh*48 + tid];
    __syncthreads();
    const float* qbase = qkv + ((size_t)(b*1152 + hd*HD)) * GN + n0;
    size_t ob = ((size_t)(b*CC + hd*HD)) * GN + n0;
    for (int j0 = 0; j0 < 392; j0 += 28) {
        for (int idx = tid; idx < 48*28; idx += 256) {
            int d = idx / 28, j = idx - d*28;
            float q = qbase[(size_t)d*GN + j0 + j];
            qp_s[j*49 + d] = phi_f(q);
        }
        __syncthreads();
        if (tid < 28) {
            float s = 0.f;
            #pragma unroll
            for (int d = 0; d < 48; d++) s = fmaf(qp_s[tid*49 + d], ks_s[d], s);
            dinv[tid] = 1.f / (s + 1e-6f);
        }
        __syncthreads();
        for (int idx = tid; idx < 48*28; idx += 256) {
            int e = idx / 28, j = idx - e*28;
            float s = 0.f;
            #pragma unroll
            for (int d = 0; d < 48; d++) s = fmaf(qp_s[j*49 + d], kv_s[d*48 + e], s);
            float v = s * dinv[j];
            bf16 hh, ll; split2(v, hh, ll);
            oh[ob + (size_t)e*GN + j0 + j] = hh;
            ol[ob + (size_t)e*GN + j0 + j] = ll;
        }
        __syncthreads();
    }
}

// ---------------- LayerNorm over channels, writes bf16 hi/lo ----------------
__global__ __launch_bounds__(256)
void ln_kernel(const float* __restrict__ x2, const float* __restrict__ lw,
               const float* __restrict__ lb, bf16* __restrict__ oh, bf16* __restrict__ ol) {
    int b = blockIdx.y; int n0 = blockIdx.x * 16;
    __shared__ float s[CC*17];
    __shared__ float r1[256], r2[256];
    __shared__ float mu[16], ri[16];
    const float* base = x2 + (size_t)b * CC * GN + n0;
    int tid = threadIdx.x;
    for (int idx = tid; idx < CC*16; idx += 256) {
        int c = idx >> 4, j = idx & 15;
        s[c*17 + j] = base[(size_t)c * GN + j];
    }
    __syncthreads();
    {
        int j = tid & 15, part = tid >> 4;
        float sm = 0.f, sq = 0.f;
        for (int c = part*24; c < part*24 + 24; c++) {
            float v = s[c*17 + j]; sm += v; sq = fmaf(v, v, sq);
        }
        r1[tid] = sm; r2[tid] = sq;
    }
    __syncthreads();
    if (tid < 16) {
        float a = 0.f, q = 0.f;
        #pragma unroll
        for (int p = 0; p < 16; p++) { a += r1[p*16 + tid]; q += r2[p*16 + tid]; }
        float mean = a * (1.f/384.f);
        float var = q * (1.f/384.f) - mean*mean;
        mu[tid] = mean; ri[tid] = rsqrtf(var + 1e-5f);
    }
    __syncthreads();
    size_t ob = (size_t)b * CC * GN + n0;
    for (int idx = tid; idx < CC*16; idx += 256) {
        int c = idx >> 4, j = idx & 15;
        float v = (s[c*17 + j] - mu[j]) * ri[j] * lw[c] + lb[c];
        bf16 hh, ll; split2(v, hh, ll);
        oh[ob + (size_t)c * GN + j] = hh;
        ol[ob + (size_t)c * GN + j] = ll;
    }
}

// ---------------- launch ----------------
extern "C" void kernel_launch(void* const* d_in, const int* in_sizes, int n_in,
                              void* d_out, int out_size) {
    const float* x      = (const float*)d_in[0];
    const float* bn1_w  = (const float*)d_in[1];
    const float* bn1_b  = (const float*)d_in[2];
    const float* bn1_m  = (const float*)d_in[3];
    const float* bn1_v  = (const float*)d_in[4];
    const float* cw1    = (const float*)d_in[5];
    const float* cb1    = (const float*)d_in[6];
    const float* dw     = (const float*)d_in[7];
    const float* db     = (const float*)d_in[8];
    const float* bn2_w  = (const float*)d_in[9];
    const float* bn2_b  = (const float*)d_in[10];
    const float* bn2_m  = (const float*)d_in[11];
    const float* bn2_v  = (const float*)d_in[12];
    const float* cw2    = (const float*)d_in[13];
    const float* cb2    = (const float*)d_in[14];
    const float* qkv_w  = (const float*)d_in[15];
    const float* proj_w = (const float*)d_in[16];
    const float* proj_b = (const float*)d_in[17];
    const float* ln_w   = (const float*)d_in[18];
    const float* ln_b   = (const float*)d_in[19];
    const float* mlp_w1 = (const float*)d_in[20];
    const float* mlp_b1 = (const float*)d_in[21];
    const float* mlp_w2 = (const float*)d_in[22];
    const float* mlp_b2 = (const float*)d_in[23];

    // symbol addresses
    float *bufA, *x1, *x2, *qkvb, *w1f, *b1f, *w1t, *w2t;
    bf16 *xh,*xl,*dwh,*dwl,*x1h,*x1l,*aoh,*aol,*lnh,*lnl,*hmh,*hml;
    bf16 *w1fh,*w1fl,*cw2h,*cw2l,*qkvh,*qkvl,*projh,*projl,*w1th,*w1tl,*w2th,*w2tl;
    cudaGetSymbolAddress((void**)&bufA, g_bufA);
    cudaGetSymbolAddress((void**)&x1,   g_x1b);
    cudaGetSymbolAddress((void**)&x2,   g_x2b);
    cudaGetSymbolAddress((void**)&qkvb, g_qkvb);
    cudaGetSymbolAddress((void**)&w1f,  g_w1f);
    cudaGetSymbolAddress((void**)&b1f,  g_b1f);
    cudaGetSymbolAddress((void**)&w1t,  g_w1t);
    cudaGetSymbolAddress((void**)&w2t,  g_w2t);
    cudaGetSymbolAddress((void**)&xh,  g_xh);   cudaGetSymbolAddress((void**)&xl,  g_xl);
    cudaGetSymbolAddress((void**)&dwh, g_dwh);  cudaGetSymbolAddress((void**)&dwl, g_dwl);
    cudaGetSymbolAddress((void**)&x1h, g_x1h);  cudaGetSymbolAddress((void**)&x1l, g_x1l);
    cudaGetSymbolAddress((void**)&aoh, g_aoh);  cudaGetSymbolAddress((void**)&aol, g_aol);
    cudaGetSymbolAddress((void**)&lnh, g_lnh);  cudaGetSymbolAddress((void**)&lnl, g_lnl);
    cudaGetSymbolAddress((void**)&hmh, g_hmh);  cudaGetSymbolAddress((void**)&hml, g_hml);
    cudaGetSymbolAddress((void**)&w1fh, g_w1fh); cudaGetSymbolAddress((void**)&w1fl, g_w1fl);
    cudaGetSymbolAddress((void**)&cw2h, g_cw2h); cudaGetSymbolAddress((void**)&cw2l, g_cw2l);
    cudaGetSymbolAddress((void**)&qkvh, g_qkvh); cudaGetSymbolAddress((void**)&qkvl, g_qkvl);
    cudaGetSymbolAddress((void**)&projh, g_projh); cudaGetSymbolAddress((void**)&projl, g_projl);
    cudaGetSymbolAddress((void**)&w1th, g_w1th); cudaGetSymbolAddress((void**)&w1tl, g_w1tl);
    cudaGetSymbolAddress((void**)&w2th, g_w2th); cudaGetSymbolAddress((void**)&w2tl, g_w2tl);

    // weight prep
    fold_bn1_kernel<<<CC, 128>>>(cw1, cb1, bn1_w, bn1_b, bn1_m, bn1_v);
    fold_bn2_kernel<<<2, 192>>>(dw, db, bn2_w, bn2_b, bn2_m, bn2_v);
    transpose_kernel<<<(CC*4*CC + 255)/256, 256>>>(mlp_w1, w1t, CC, 4*CC);
    transpose_kernel<<<(CC*4*CC + 255)/256, 256>>>(mlp_w2, w2t, 4*CC, CC);
    split_kernel<<<(CC*CC + 255)/256, 256>>>(w1f, w1fh, w1fl, CC*CC);
    split_kernel<<<(CC*CC + 255)/256, 256>>>(cw2, cw2h, cw2l, CC*CC);
    split_kernel<<<(3*CC*CC + 255)/256, 256>>>(qkv_w, qkvh, qkvl, 3*CC*CC);
    split_kernel<<<(CC*CC + 255)/256, 256>>>(proj_w, projh, projl, CC*CC);
    split_kernel<<<(CC*4*CC + 255)/256, 256>>>(w1t, w1th, w1tl, CC*4*CC);
    split_kernel<<<(CC*4*CC + 255)/256, 256>>>(w2t, w2th, w2tl, CC*4*CC);
    split_kernel<<<(SZ + 255)/256, 256>>>(x, xh, xl, SZ);
    zero_kv_kernel<<<(BB*NHEADS*HD*HD + 255)/256, 256>>>();

    // conv path
    run_gemm(w1fh, w1fl, xh, xl, b1f, nullptr, bufA, nullptr, nullptr, CC, CC, 0);
    dwconv_kernel<<<BB*CC, 256>>>(bufA, dwh, dwl);
    run_gemm(cw2h, cw2l, dwh, dwl, cb2, x, x1, x1h, x1l, CC, CC, 0);   // x1 = 1x1 + x (fp32 + hi/lo)

    // linear attention
    run_gemm(qkvh, qkvl, x1h, x1l, nullptr, nullptr, qkvb, nullptr, nullptr, 3*CC, CC, 0);
    attn_kv_kernel<<<dim3(BB*NHEADS, 8), 256>>>(qkvb);
    attn_out_kernel<<<dim3(BB*NHEADS, 8), 256>>>(qkvb, aoh, aol);
    run_gemm(projh, projl, aoh, aol, proj_b, x1, x2, nullptr, nullptr, CC, CC, 0);  // x2 = proj + x1

    // LN + MLP
    ln_kernel<<<dim3(GN/16, BB), 256>>>(x2, ln_w, ln_b, lnh, lnl);
    run_gemm(w1th, w1tl, lnh, lnl, mlp_b1, nullptr, nullptr, hmh, hml, 4*CC, CC, 1);  // gelu(fc1) -> hi/lo only
    run_gemm(w2th, w2tl, hmh, hml, mlp_b2, x2, (float*)d_out, nullptr, nullptr, CC, 4*CC, 0);
}

// round 9
// speedup vs baseline: 1.2125x; 1.2125x over previous
#include <cuda_runtime.h>
#include <cuda_fp16.h>
#include <math.h>
#include <stdint.h>

#define GN 3136          // H*W
#define CC 384
#define BB 8
#define NHEADS 8
#define HD 48
#define SZ (BB*CC*GN)    // 9,633,792

typedef __half h16;

// ---------------- scratch (static device globals; no runtime alloc) ----------------
__device__ __align__(16) float g_bufA[SZ];       // conv mid (fp32, dwconv input)
__device__ __align__(16) float g_x1b[SZ];        // x1 fp32
__device__ __align__(16) float g_x2b[SZ];        // x2 fp32
__device__ __align__(16) float g_qkvb[3*SZ];     // qkv fp32
__device__ __align__(16) float g_w1f[CC*CC];
__device__ __align__(16) float g_b1f[CC];
__device__ __align__(16) float g_dwf[CC*9];
__device__ __align__(16) float g_dbf[CC];
__device__ __align__(16) float g_kv[BB*NHEADS*HD*HD];
__device__ __align__(16) float g_ksum[BB*NHEADS*HD];

// fp16 activation buffers (hi, and lo only where 3-term consumers need it)
__device__ __align__(16) h16 g_xh[SZ];
__device__ __align__(16) h16 g_dwh[SZ],  g_dwl[SZ];
__device__ __align__(16) h16 g_x1h[SZ],  g_x1l[SZ];
__device__ __align__(16) h16 g_aoh[SZ],  g_aol[SZ];
__device__ __align__(16) h16 g_lnh[SZ];
__device__ __align__(16) h16 g_hmh[4*SZ];
// fp16 hi/lo weights (A side always fully split)
__device__ __align__(16) h16 g_w1fh[CC*CC],   g_w1fl[CC*CC];
__device__ __align__(16) h16 g_cw2h[CC*CC],   g_cw2l[CC*CC];
__device__ __align__(16) h16 g_qkvh[3*CC*CC], g_qkvl[3*CC*CC];
__device__ __align__(16) h16 g_projh[CC*CC],  g_projl[CC*CC];
__device__ __align__(16) h16 g_w1th[CC*4*CC], g_w1tl[CC*4*CC];
__device__ __align__(16) h16 g_w2th[CC*4*CC], g_w2tl[CC*4*CC];

// ---------------- helpers ----------------
__device__ __forceinline__ void split2(float x, h16& h, h16& l) {
    h = __float2half_rn(x);
    l = __float2half_rn(x - __half2float(h));
}

__device__ __forceinline__ void ldsm4(uint32_t* r, uint32_t a) {
    asm volatile("ldmatrix.sync.aligned.m8n8.x4.shared.b16 {%0,%1,%2,%3}, [%4];"
                 : "=r"(r[0]), "=r"(r[1]), "=r"(r[2]), "=r"(r[3]) : "r"(a));
}
__device__ __forceinline__ void ldsm4t(uint32_t* r, uint32_t a) {
    asm volatile("ldmatrix.sync.aligned.m8n8.x4.trans.shared.b16 {%0,%1,%2,%3}, [%4];"
                 : "=r"(r[0]), "=r"(r[1]), "=r"(r[2]), "=r"(r[3]) : "r"(a));
}
__device__ __forceinline__ void mma16816(float* c, const uint32_t* a, const uint32_t* b) {
    asm volatile("mma.sync.aligned.m16n8k16.row.col.f32.f16.f16.f32 "
                 "{%0,%1,%2,%3}, {%4,%5,%6,%7}, {%8,%9}, {%0,%1,%2,%3};"
                 : "+f"(c[0]), "+f"(c[1]), "+f"(c[2]), "+f"(c[3])
                 : "r"(a[0]), "r"(a[1]), "r"(a[2]), "r"(a[3]), "r"(b[0]), "r"(b[1]));
}
__device__ __forceinline__ void cpa16(uint32_t dst, const void* src) {
    asm volatile("cp.async.ca.shared.global [%0], [%1], 16;" :: "r"(dst), "l"(src));
}

// ---------------- BN folding / prep ----------------
__global__ void fold_bn1_kernel(const float* __restrict__ cw1, const float* __restrict__ cb1,
                                const float* __restrict__ w, const float* __restrict__ bvec,
                                const float* __restrict__ m, const float* __restrict__ v) {
    int o = blockIdx.x;
    int tid = threadIdx.x;   // 128
    float part = 0.f;
    for (int i = tid; i < CC; i += 128) {
        float s = w[i] * rsqrtf(v[i] + 1e-5f);
        float t = bvec[i] - m[i] * s;
        float cv = cw1[o*CC + i];
        g_w1f[o*CC + i] = cv * s;
        part += cv * t;
    }
    __shared__ float red[128];
    red[tid] = part; __syncthreads();
    for (int st = 64; st > 0; st >>= 1) { if (tid < st) red[tid] += red[tid+st]; __syncthreads(); }
    if (tid == 0) g_b1f[o] = cb1[o] + red[0];
}

__global__ void fold_bn2_kernel(const float* __restrict__ dw, const float* __restrict__ db,
                                const float* __restrict__ w, const float* __restrict__ bvec,
                                const float* __restrict__ m, const float* __restrict__ v) {
    int c = blockIdx.x * blockDim.x + threadIdx.x;
    if (c < CC) {
        float s = w[c] * rsqrtf(v[c] + 1e-5f);
        float t = bvec[c] - m[c] * s;
        #pragma unroll
        for (int k = 0; k < 9; k++) g_dwf[c*9 + k] = dw[c*9 + k] * s;
        g_dbf[c] = db[c] * s + t;
    }
}

// transpose + split: dsth/dstl[a*srows+b] = split(src[b*scols+a])
__global__ void transpose_split_kernel(const float* __restrict__ src,
                                       h16* __restrict__ dh, h16* __restrict__ dl,
                                       int srows, int scols) {
    int idx = blockIdx.x * 256 + threadIdx.x;
    if (idx < srows * scols) {
        int a = idx / srows;
        int b = idx - a * srows;
        h16 hh, ll; split2(src[b * scols + a], hh, ll);
        dh[idx] = hh; dl[idx] = ll;
    }
}

__global__ void split_kernel(const float* __restrict__ src, h16* __restrict__ h,
                             h16* __restrict__ l, int n) {
    int i = blockIdx.x * 256 + threadIdx.x;
    if (i < n) {
        h16 hh, ll;
        split2(src[i], hh, ll);
        h[i] = hh;
        if (l) l[i] = ll;
    }
}

__global__ void zero_kv_kernel() {
    int i = blockIdx.x * 256 + threadIdx.x;
    if (i < BB*NHEADS*HD*HD) g_kv[i] = 0.f;
    if (i < BB*NHEADS*HD)    g_ksum[i] = 0.f;
}

// ---------------- fp16 split GEMM (tensor core, mma.sync) ----------------
// Y[b,o,n] = act(W[o,:]·X[b,:,n] + bias[o]) (+ res)
// TERMS==3: Ah·Bh + Ah·Bl + Al·Bh (err ~2^-22). TERMS==2: Ah·Bh + Al·Bh (err ~2^-11, Xl unused).
// BM=128, BN=64, BK=32, 128 threads, 4 warps (2m x 2n), warp tile 64x32.
#define SM_A    0
#define SM_BH   16384
#define SM_BL   20480
#define SM_BUF  24576

template<int ACT, int TERMS>
__global__ __launch_bounds__(128)
void gemm_f16(const h16* __restrict__ Wh, const h16* __restrict__ Wl,
              const h16* __restrict__ Xh, const h16* __restrict__ Xl,
              const float* __restrict__ bias, const float* __restrict__ res,
              float* __restrict__ YF, h16* __restrict__ YH, h16* __restrict__ YL,
              int Cout, int K) {
    const int b  = blockIdx.z;
    const int m0 = blockIdx.y * 128;
    const int n0 = blockIdx.x * 64;
    const h16* Xhb = Xh + (size_t)b * K * GN;
    const h16* Xlb = (TERMS == 3) ? Xl + (size_t)b * K * GN : Xhb;
    const size_t obase = (size_t)b * Cout * GN;

    __shared__ __align__(16) unsigned char smraw[2 * SM_BUF];
    const uint32_t smbase = (uint32_t)__cvta_generic_to_shared(smraw);

    const int tid  = threadIdx.x;
    const int lane = tid & 31;
    const int wid  = tid >> 5;
    const int warp_m = wid & 1;        // 2
    const int warp_n = wid >> 1;       // 2
    const int m_base = warp_m * 64;
    const int n_base = warp_n * 32;

    const int r8   = (lane & 7) + ((lane >> 3) & 1) * 8;
    const int cadd = lane >> 4;

    float acc[4][4][4];
    #pragma unroll
    for (int i = 0; i < 4; i++)
        #pragma unroll
        for (int nt = 0; nt < 4; nt++)
            #pragma unroll
            for (int q = 0; q < 4; q++) acc[i][nt][q] = 0.f;

    const int cpc = tid & 7;           // chunk 0..7
    const int cpm = tid >> 3;          // base row 0..15

    auto issue_tile = [&](int k0, int buf) {
        uint32_t sb = smbase + buf * SM_BUF;
        #pragma unroll
        for (int h = 0; h < 8; h++) {
            int m = cpm + 16*h;                          // 0..127
            uint32_t d = sb + SM_A + m*128 + ((cpc ^ (m & 7)) << 4);
            const h16* s = (cpc < 4)
                ? (Wh + (size_t)(m0 + m) * K + k0 + cpc*8)
                : (Wl + (size_t)(m0 + m) * K + k0 + (cpc - 4)*8);
            cpa16(d, s);
        }
        #pragma unroll
        for (int h = 0; h < (TERMS == 3 ? 4 : 2); h++) {
            int k = cpm + 16*(h & 1);                    // 0..31
            bool hi = (h < 2);
            uint32_t d = sb + (hi ? SM_BH : SM_BL) + k*128 + ((cpc ^ (k & 7)) << 4);
            const h16* s = (hi ? Xhb : Xlb) + (size_t)(k0 + k) * GN + n0 + cpc*8;
            cpa16(d, s);
        }
        asm volatile("cp.async.commit_group;" ::: "memory");
    };

    issue_tile(0, 0);
    int cur = 0;
    for (int k0 = 0; k0 < K; k0 += 32) {
        asm volatile("cp.async.wait_group 0;" ::: "memory");
        __syncthreads();
        if (k0 + 32 < K) issue_tile(k0 + 32, cur ^ 1);
        uint32_t sb = smbase + cur * SM_BUF;

        #pragma unroll
        for (int j = 0; j < 2; j++) {                    // two k16 steps
            uint32_t ah[4][4], al[4][4], bh[4][2], bl[4][2];
            #pragma unroll
            for (int i = 0; i < 4; i++) {
                int row = m_base + 16*i + r8;
                int ch = 2*j + cadd;
                ldsm4(ah[i], sb + SM_A + row*128 + ((ch ^ (row & 7)) << 4));
                int cl = 4 + 2*j + cadd;
                ldsm4(al[i], sb + SM_A + row*128 + ((cl ^ (row & 7)) << 4));
            }
            #pragma unroll
            for (int u = 0; u < 2; u++) {
                int rowk = 16*j + r8;
                int nc = warp_n*4 + 2*u + cadd;
                uint32_t t[4];
                ldsm4t(t, sb + SM_BH + rowk*128 + ((nc ^ (rowk & 7)) << 4));
                bh[2*u][0] = t[0]; bh[2*u][1] = t[1];
                bh[2*u+1][0] = t[2]; bh[2*u+1][1] = t[3];
                if (TERMS == 3) {
                    ldsm4t(t, sb + SM_BL + rowk*128 + ((nc ^ (rowk & 7)) << 4));
                    bl[2*u][0] = t[0]; bl[2*u][1] = t[1];
                    bl[2*u+1][0] = t[2]; bl[2*u+1][1] = t[3];
                }
            }
            #pragma unroll
            for (int i = 0; i < 4; i++)
                #pragma unroll
                for (int nt = 0; nt < 4; nt++) {
                    mma16816(acc[i][nt], ah[i], bh[nt]);
                    if (TERMS == 3) mma16816(acc[i][nt], ah[i], bl[nt]);
                    mma16816(acc[i][nt], al[i], bh[nt]);
                }
        }
        cur ^= 1;
    }

    // epilogue
    const int g = lane >> 2, tc = lane & 3;
    #pragma unroll
    for (int i = 0; i < 4; i++) {
        #pragma unroll
        for (int half = 0; half < 2; half++) {
            int row = m0 + m_base + 16*i + g + 8*half;
            float bv = bias ? bias[row] : 0.f;
            size_t rowoff = obase + (size_t)row * GN;
            #pragma unroll
            for (int nt = 0; nt < 4; nt++) {
                int n = n0 + n_base + 8*nt + tc*2;
                float v0 = acc[i][nt][2*half + 0] + bv;
                float v1 = acc[i][nt][2*half + 1] + bv;
                if (ACT == 1) {
                    v0 = 0.5f * v0 * (1.f + erff(v0 * 0.70710678118654752f));
                    v1 = 0.5f * v1 * (1.f + erff(v1 * 0.70710678118654752f));
                }
                if (res) {
                    float2 r = *reinterpret_cast<const float2*>(res + rowoff + n);
                    v0 += r.x; v1 += r.y;
                }
                if (YF) *reinterpret_cast<float2*>(YF + rowoff + n) = make_float2(v0, v1);
                if (YH) {
                    h16 h0, l0, h1, l1;
                    split2(v0, h0, l0); split2(v1, h1, l1);
                    __half2 ph; ph.x = h0; ph.y = h1;
                    *reinterpret_cast<__half2*>(YH + rowoff + n) = ph;
                    if (YL) {
                        __half2 pl; pl.x = l0; pl.y = l1;
                        *reinterpret_cast<__half2*>(YL + rowoff + n) = pl;
                    }
                }
            }
        }
    }
}

template<int ACT, int TERMS>
static void run_gemm(const h16* Wh, const h16* Wl, const h16* Xh, const h16* Xl,
                     const float* bias, const float* res,
                     float* YF, h16* YH, h16* YL, int Cout, int K) {
    dim3 g(GN/64, Cout/128, BB), blk(128);
    gemm_f16<ACT, TERMS><<<g, blk>>>(Wh, Wl, Xh, Xl, bias, res, YF, YH, YL, Cout, K);
}

// ---------------- depthwise 3x3 (BN2-folded), writes fp16 hi/lo ----------------
__global__ __launch_bounds__(256)
void dwconv_kernel(const float* __restrict__ in, h16* __restrict__ oh, h16* __restrict__ ol) {
    int bc = blockIdx.x;          // b*CC + c
    int c  = bc % CC;
    __shared__ float tile[58*58];
    const float* plane = in + (size_t)bc * GN;
    int tid = threadIdx.x;
    for (int idx = tid; idx < 58*58; idx += 256) {
        int ty = idx / 58, tx = idx - ty*58;
        int y = ty - 1, xq = tx - 1;
        float v = 0.f;
        if (y >= 0 && y < 56 && xq >= 0 && xq < 56) v = plane[y*56 + xq];
        tile[idx] = v;
    }
    __syncthreads();
    float w0=g_dwf[c*9+0], w1=g_dwf[c*9+1], w2=g_dwf[c*9+2];
    float w3=g_dwf[c*9+3], w4=g_dwf[c*9+4], w5=g_dwf[c*9+5];
    float w6=g_dwf[c*9+6], w7=g_dwf[c*9+7], w8=g_dwf[c*9+8];
    float bbv = g_dbf[c];
    h16* ohp = oh + (size_t)bc * GN;
    h16* olp = ol + (size_t)bc * GN;
    for (int p = tid; p < GN; p += 256) {
        int y = p / 56, xq = p - y*56;
        const float* t = &tile[y*58 + xq];
        float a = bbv + w0*t[0] + w1*t[1] + w2*t[2]
                      + w3*t[58] + w4*t[59] + w5*t[60]
                      + w6*t[116] + w7*t[117] + w8*t[118];
        h16 hh, ll; split2(a, hh, ll);
        ohp[p] = hh; olp[p] = ll;
    }
}

// ---------------- linear attention ----------------
__device__ __forceinline__ float phi_f(float t) { return expf(0.5f * (2.f*t - t*t)); }

__global__ __launch_bounds__(256)
void attn_kv_kernel(const float* __restrict__ qkv) {
    int bh = blockIdx.x; int b = bh >> 3, hd = bh & 7;
    int n0 = blockIdx.y * 392;
    __shared__ float kp_s[28*48];
    __shared__ float vv_s[28*48];
    int tid = threadIdx.x;
    int dr[9], er[9];
    #pragma unroll
    for (int r = 0; r < 9; r++) { int de = tid + 256*r; dr[r] = de/48; er[r] = de - dr[r]*48; }
    float acc[9];
    #pragma unroll
    for (int r = 0; r < 9; r++) acc[r] = 0.f;
    float ks = 0.f;
    const float* kbase = qkv + ((size_t)(b*1152 + CC   + hd*HD)) * GN + n0;
    const float* vbase = qkv + ((size_t)(b*1152 + 2*CC + hd*HD)) * GN + n0;
    for (int j0 = 0; j0 < 392; j0 += 28) {
        for (int idx = tid; idx < 48*28; idx += 256) {
            int d = idx / 28, j = idx - d*28;
            float kvl = kbase[(size_t)d*GN + j0 + j];
            kp_s[j*48 + d] = phi_f(kvl);
            vv_s[j*48 + d] = vbase[(size_t)d*GN + j0 + j];
        }
        __syncthreads();
        #pragma unroll 4
        for (int j = 0; j < 28; j++) {
            #pragma unroll
            for (int r = 0; r < 9; r++)
                acc[r] = fmaf(kp_s[j*48 + dr[r]], vv_s[j*48 + er[r]], acc[r]);
        }
        if (tid < 48) {
            float s = 0.f;
            #pragma unroll 4
            for (int j = 0; j < 28; j++) s += kp_s[j*48 + tid];
            ks += s;
        }
        __syncthreads();
    }
    #pragma unroll
    for (int r = 0; r < 9; r++) atomicAdd(&g_kv[bh*2304 + tid + 256*r], acc[r]);
    if (tid < 48) atomicAdd(&g_ksum[bh*48 + tid], ks);
}

__global__ __launch_bounds__(256)
void attn_out_kernel(const float* __restrict__ qkv,
                     h16* __restrict__ oh, h16* __restrict__ ol) {
    int bh = blockIdx.x; int b = bh >> 3, hd = bh & 7;
    int n0 = blockIdx.y * 392;
    __shared__ float kv_s[2304];
    __shared__ float ks_s[48];
    __shared__ float qp_s[28*49];
    __shared__ float dinv[28];
    int tid = threadIdx.x;
    for (int i = tid; i < 2304; i += 256) kv_s[i] = g_kv[bh*2304 + i];
    if (tid < 48) ks_s[tid] = g_ksum[bh*48 + tid];
    __syncthreads();
    const float* qbase = qkv + ((size_t)(b*1152 + hd*HD)) * GN + n0;
    size_t ob = ((size_t)(b*CC + hd*HD)) * GN + n0;
    for (int j0 = 0; j0 < 392; j0 += 28) {
        for (int idx = tid; idx < 48*28; idx += 256) {
            int d = idx / 28, j = idx - d*28;
            float q = qbase[(size_t)d*GN + j0 + j];
            qp_s[j*49 + d] = phi_f(q);
        }
        __syncthreads();
        if (tid < 28) {
            float s = 0.f;
            #pragma unroll
            for (int d = 0; d < 48; d++) s = fmaf(qp_s[tid*49 + d], ks_s[d], s);
            dinv[tid] = 1.f / (s + 1e-6f);
        }
        __syncthreads();
        for (int idx = tid; idx < 48*28; idx += 256) {
            int e = idx / 28, j = idx - e*28;
            float s = 0.f;
            #pragma unroll
            for (int d = 0; d < 48; d++) s = fmaf(qp_s[j*49 + d], kv_s[d*48 + e], s);
            float v = s * dinv[j];
            h16 hh, ll; split2(v, hh, ll);
            oh[ob + (size_t)e*GN + j0 + j] = hh;
            ol[ob + (size_t)e*GN + j0 + j] = ll;
        }
        __syncthreads();
    }
}

// ---------------- LayerNorm over channels, writes fp16 hi only ----------------
__global__ __launch_bounds__(256)
void ln_kernel(const float* __restrict__ x2, const float* __restrict__ lw,
               const float* __restrict__ lb, h16* __restrict__ oh) {
    int b = blockIdx.y; int n0 = blockIdx.x * 16;
    __shared__ float s[CC*17];
    __shared__ float r1[256], r2[256];
    __shared__ float mu[16], ri[16];
    const float* base = x2 + (size_t)b * CC * GN + n0;
    int tid = threadIdx.x;
    for (int idx = tid; idx < CC*16; idx += 256) {
        int c = idx >> 4, j = idx & 15;
        s[c*17 + j] = base[(size_t)c * GN + j];
    }
    __syncthreads();
    {
        int j = tid & 15, part = tid >> 4;
        float sm = 0.f, sq = 0.f;
        for (int c = part*24; c < part*24 + 24; c++) {
            float v = s[c*17 + j]; sm += v; sq = fmaf(v, v, sq);
        }
        r1[tid] = sm; r2[tid] = sq;
    }
    __syncthreads();
    if (tid < 16) {
        float a = 0.f, q = 0.f;
        #pragma unroll
        for (int p = 0; p < 16; p++) { a += r1[p*16 + tid]; q += r2[p*16 + tid]; }
        float mean = a * (1.f/384.f);
        float var = q * (1.f/384.f) - mean*mean;
        mu[tid] = mean; ri[tid] = rsqrtf(var + 1e-5f);
    }
    __syncthreads();
    size_t ob = (size_t)b * CC * GN + n0;
    for (int idx = tid; idx < CC*16; idx += 256) {
        int c = idx >> 4, j = idx & 15;
        float v = (s[c*17 + j] - mu[j]) * ri[j] * lw[c] + lb[c];
        oh[ob + (size_t)c * GN + j] = __float2half_rn(v);
    }
}

// ---------------- launch ----------------
extern "C" void kernel_launch(void* const* d_in, const int* in_sizes, int n_in,
                              void* d_out, int out_size) {
    const float* x      = (const float*)d_in[0];
    const float* bn1_w  = (const float*)d_in[1];
    const float* bn1_b  = (const float*)d_in[2];
    const float* bn1_m  = (const float*)d_in[3];
    const float* bn1_v  = (const float*)d_in[4];
    const float* cw1    = (const float*)d_in[5];
    const float* cb1    = (const float*)d_in[6];
    const float* dw     = (const float*)d_in[7];
    const float* db     = (const float*)d_in[8];
    const float* bn2_w  = (const float*)d_in[9];
    const float* bn2_b  = (const float*)d_in[10];
    const float* bn2_m  = (const float*)d_in[11];
    const float* bn2_v  = (const float*)d_in[12];
    const float* cw2    = (const float*)d_in[13];
    const float* cb2    = (const float*)d_in[14];
    const float* qkv_w  = (const float*)d_in[15];
    const float* proj_w = (const float*)d_in[16];
    const float* proj_b = (const float*)d_in[17];
    const float* ln_w   = (const float*)d_in[18];
    const float* ln_b   = (const float*)d_in[19];
    const float* mlp_w1 = (const float*)d_in[20];
    const float* mlp_b1 = (const float*)d_in[21];
    const float* mlp_w2 = (const float*)d_in[22];
    const float* mlp_b2 = (const float*)d_in[23];

    // symbol addresses
    float *bufA, *x1, *x2, *qkvb, *w1f, *b1f;
    h16 *xh,*dwh,*dwl,*x1h,*x1l,*aoh,*aol,*lnh,*hmh;
    h16 *w1fh,*w1fl,*cw2h,*cw2l,*qkvh,*qkvl,*projh,*projl,*w1th,*w1tl,*w2th,*w2tl;
    cudaGetSymbolAddress((void**)&bufA, g_bufA);
    cudaGetSymbolAddress((void**)&x1,   g_x1b);
    cudaGetSymbolAddress((void**)&x2,   g_x2b);
    cudaGetSymbolAddress((void**)&qkvb, g_qkvb);
    cudaGetSymbolAddress((void**)&w1f,  g_w1f);
    cudaGetSymbolAddress((void**)&b1f,  g_b1f);
    cudaGetSymbolAddress((void**)&xh,  g_xh);
    cudaGetSymbolAddress((void**)&dwh, g_dwh);  cudaGetSymbolAddress((void**)&dwl, g_dwl);
    cudaGetSymbolAddress((void**)&x1h, g_x1h);  cudaGetSymbolAddress((void**)&x1l, g_x1l);
    cudaGetSymbolAddress((void**)&aoh, g_aoh);  cudaGetSymbolAddress((void**)&aol, g_aol);
    cudaGetSymbolAddress((void**)&lnh, g_lnh);
    cudaGetSymbolAddress((void**)&hmh, g_hmh);
    cudaGetSymbolAddress((void**)&w1fh, g_w1fh); cudaGetSymbolAddress((void**)&w1fl, g_w1fl);
    cudaGetSymbolAddress((void**)&cw2h, g_cw2h); cudaGetSymbolAddress((void**)&cw2l, g_cw2l);
    cudaGetSymbolAddress((void**)&qkvh, g_qkvh); cudaGetSymbolAddress((void**)&qkvl, g_qkvl);
    cudaGetSymbolAddress((void**)&projh, g_projh); cudaGetSymbolAddress((void**)&projl, g_projl);
    cudaGetSymbolAddress((void**)&w1th, g_w1th); cudaGetSymbolAddress((void**)&w1tl, g_w1tl);
    cudaGetSymbolAddress((void**)&w2th, g_w2th); cudaGetSymbolAddress((void**)&w2tl, g_w2tl);

    // weight prep
    fold_bn1_kernel<<<CC, 128>>>(cw1, cb1, bn1_w, bn1_b, bn1_m, bn1_v);
    fold_bn2_kernel<<<2, 192>>>(dw, db, bn2_w, bn2_b, bn2_m, bn2_v);
    transpose_split_kernel<<<(CC*4*CC + 255)/256, 256>>>(mlp_w1, w1th, w1tl, CC, 4*CC);
    transpose_split_kernel<<<(CC*4*CC + 255)/256, 256>>>(mlp_w2, w2th, w2tl, 4*CC, CC);
    split_kernel<<<(CC*CC + 255)/256, 256>>>(w1f, w1fh, w1fl, CC*CC);
    split_kernel<<<(CC*CC + 255)/256, 256>>>(cw2, cw2h, cw2l, CC*CC);
    split_kernel<<<(3*CC*CC + 255)/256, 256>>>(qkv_w, qkvh, qkvl, 3*CC*CC);
    split_kernel<<<(CC*CC + 255)/256, 256>>>(proj_w, projh, projl, CC*CC);
    split_kernel<<<(SZ + 255)/256, 256>>>(x, xh, nullptr, SZ);   // hi only (cw1 is 2-term)
    zero_kv_kernel<<<(BB*NHEADS*HD*HD + 255)/256, 256>>>();

    // conv path
    run_gemm<0,2>(w1fh, w1fl, xh, nullptr, b1f, nullptr, bufA, nullptr, nullptr, CC, CC);
    dwconv_kernel<<<BB*CC, 256>>>(bufA, dwh, dwl);
    run_gemm<0,3>(cw2h, cw2l, dwh, dwl, cb2, x, x1, x1h, x1l, CC, CC);   // x1 = 1x1 + x

    // linear attention
    run_gemm<0,3>(qkvh, qkvl, x1h, x1l, nullptr, nullptr, qkvb, nullptr, nullptr, 3*CC, CC);
    attn_kv_kernel<<<dim3(BB*NHEADS, 8), 256>>>(qkvb);
    attn_out_kernel<<<dim3(BB*NHEADS, 8), 256>>>(qkvb, aoh, aol);
    run_gemm<0,3>(projh, projl, aoh, aol, proj_b, x1, x2, nullptr, nullptr, CC, CC);  // x2 = proj + x1

    // LN + MLP
    ln_kernel<<<dim3(GN/16, BB), 256>>>(x2, ln_w, ln_b, lnh);
    run_gemm<1,2>(w1th, w1tl, lnh, nullptr, mlp_b1, nullptr, nullptr, hmh, nullptr, 4*CC, CC);  // gelu(fc1)
    run_gemm<0,2>(w2th, w2tl, hmh, nullptr, mlp_b2, x2, (float*)d_out, nullptr, nullptr, CC, 4*CC);
}

// round 10
// speedup vs baseline: 1.3450x; 1.1092x over previous
#include <cuda_runtime.h>
#include <cuda_fp16.h>
#include <math.h>
#include <stdint.h>

#define GN 3136          // H*W
#define CC 384
#define BB 8
#define NHEADS 8
#define HD 48
#define SZ (BB*CC*GN)    // 9,633,792

typedef __half h16;

// ---------------- scratch (static device globals; no runtime alloc) ----------------
__device__ __align__(16) float g_bufA[SZ];       // conv mid (fp32, dwconv input)
__device__ __align__(16) float g_x1b[SZ];        // x1 fp32
__device__ __align__(16) float g_x2b[SZ];        // x2 fp32
__device__ __align__(16) float g_w1f[CC*CC];
__device__ __align__(16) float g_b1f[CC];
__device__ __align__(16) float g_dwf[CC*9];
__device__ __align__(16) float g_dbf[CC];
__device__ __align__(16) float g_kv[BB*NHEADS*HD*HD];
__device__ __align__(16) float g_ksum[BB*NHEADS*HD];

// fp16 activation buffers (hi only — all GEMMs are 2-term, exact in weights)
__device__ __align__(16) h16 g_xh[SZ];
__device__ __align__(16) h16 g_dwh[SZ];
__device__ __align__(16) h16 g_x1h[SZ];
__device__ __align__(16) h16 g_qkvh16[3*SZ];
__device__ __align__(16) h16 g_aoh[SZ];
__device__ __align__(16) h16 g_lnh[SZ];
__device__ __align__(16) h16 g_hmh[4*SZ];
// fp16 hi/lo weights (A side fully split: Ah+Al == A exactly)
__device__ __align__(16) h16 g_w1fh[CC*CC],   g_w1fl[CC*CC];
__device__ __align__(16) h16 g_cw2h[CC*CC],   g_cw2l[CC*CC];
__device__ __align__(16) h16 g_qkvh[3*CC*CC], g_qkvl[3*CC*CC];
__device__ __align__(16) h16 g_projh[CC*CC],  g_projl[CC*CC];
__device__ __align__(16) h16 g_w1th[CC*4*CC], g_w1tl[CC*4*CC];
__device__ __align__(16) h16 g_w2th[CC*4*CC], g_w2tl[CC*4*CC];

// ---------------- helpers ----------------
__device__ __forceinline__ void split2(float x, h16& h, h16& l) {
    h = __float2half_rn(x);
    l = __float2half_rn(x - __half2float(h));
}

__device__ __forceinline__ void ldsm4(uint32_t* r, uint32_t a) {
    asm volatile("ldmatrix.sync.aligned.m8n8.x4.shared.b16 {%0,%1,%2,%3}, [%4];"
                 : "=r"(r[0]), "=r"(r[1]), "=r"(r[2]), "=r"(r[3]) : "r"(a));
}
__device__ __forceinline__ void ldsm4t(uint32_t* r, uint32_t a) {
    asm volatile("ldmatrix.sync.aligned.m8n8.x4.trans.shared.b16 {%0,%1,%2,%3}, [%4];"
                 : "=r"(r[0]), "=r"(r[1]), "=r"(r[2]), "=r"(r[3]) : "r"(a));
}
__device__ __forceinline__ void mma16816(float* c, const uint32_t* a, const uint32_t* b) {
    asm volatile("mma.sync.aligned.m16n8k16.row.col.f32.f16.f16.f32 "
                 "{%0,%1,%2,%3}, {%4,%5,%6,%7}, {%8,%9}, {%0,%1,%2,%3};"
                 : "+f"(c[0]), "+f"(c[1]), "+f"(c[2]), "+f"(c[3])
                 : "r"(a[0]), "r"(a[1]), "r"(a[2]), "r"(a[3]), "r"(b[0]), "r"(b[1]));
}
__device__ __forceinline__ void cpa16(uint32_t dst, const void* src) {
    asm volatile("cp.async.ca.shared.global [%0], [%1], 16;" :: "r"(dst), "l"(src));
}

// ---------------- BN folding / prep ----------------
__global__ void fold_bn1_kernel(const float* __restrict__ cw1, const float* __restrict__ cb1,
                                const float* __restrict__ w, const float* __restrict__ bvec,
                                const float* __restrict__ m, const float* __restrict__ v) {
    int o = blockIdx.x;
    int tid = threadIdx.x;   // 128
    float part = 0.f;
    for (int i = tid; i < CC; i += 128) {
        float s = w[i] * rsqrtf(v[i] + 1e-5f);
        float t = bvec[i] - m[i] * s;
        float cv = cw1[o*CC + i];
        g_w1f[o*CC + i] = cv * s;
        part += cv * t;
    }
    __shared__ float red[128];
    red[tid] = part; __syncthreads();
    for (int st = 64; st > 0; st >>= 1) { if (tid < st) red[tid] += red[tid+st]; __syncthreads(); }
    if (tid == 0) g_b1f[o] = cb1[o] + red[0];
}

__global__ void fold_bn2_kernel(const float* __restrict__ dw, const float* __restrict__ db,
                                const float* __restrict__ w, const float* __restrict__ bvec,
                                const float* __restrict__ m, const float* __restrict__ v) {
    int c = blockIdx.x * blockDim.x + threadIdx.x;
    if (c < CC) {
        float s = w[c] * rsqrtf(v[c] + 1e-5f);
        float t = bvec[c] - m[c] * s;
        #pragma unroll
        for (int k = 0; k < 9; k++) g_dwf[c*9 + k] = dw[c*9 + k] * s;
        g_dbf[c] = db[c] * s + t;
    }
}

// transpose + split: dsth/dstl[a*srows+b] = split(src[b*scols+a])
__global__ void transpose_split_kernel(const float* __restrict__ src,
                                       h16* __restrict__ dh, h16* __restrict__ dl,
                                       int srows, int scols) {
    int idx = blockIdx.x * 256 + threadIdx.x;
    if (idx < srows * scols) {
        int a = idx / srows;
        int b = idx - a * srows;
        h16 hh, ll; split2(src[b * scols + a], hh, ll);
        dh[idx] = hh; dl[idx] = ll;
    }
}

__global__ void split_kernel(const float* __restrict__ src, h16* __restrict__ h,
                             h16* __restrict__ l, int n) {
    int i = blockIdx.x * 256 + threadIdx.x;
    if (i < n) {
        h16 hh, ll;
        split2(src[i], hh, ll);
        h[i] = hh;
        if (l) l[i] = ll;
    }
}

__global__ void zero_kv_kernel() {
    int i = blockIdx.x * 256 + threadIdx.x;
    if (i < BB*NHEADS*HD*HD) g_kv[i] = 0.f;
    if (i < BB*NHEADS*HD)    g_ksum[i] = 0.f;
}

// ---------------- fp16 2-term GEMM (tensor core, mma.sync) ----------------
// Y[b,o,n] = act((Wh+Wl)[o,:]·Xh[b,:,n] + bias[o]) (+ res)  — exact in W, fp16-rounded in X.
// BM=128, BN=64, BK=32, 128 threads, 4 warps (2m x 2n), warp tile 64x32.
#define SM_A    0
#define SM_BH   16384
#define SM_BUF  20480

template<int ACT>
__global__ __launch_bounds__(128)
void gemm_f16(const h16* __restrict__ Wh, const h16* __restrict__ Wl,
              const h16* __restrict__ Xh,
              const float* __restrict__ bias, const float* __restrict__ res,
              float* __restrict__ YF, h16* __restrict__ YH,
              int Cout, int K) {
    const int b  = blockIdx.z;
    const int m0 = blockIdx.y * 128;
    const int n0 = blockIdx.x * 64;
    const h16* Xhb = Xh + (size_t)b * K * GN;
    const size_t obase = (size_t)b * Cout * GN;

    __shared__ __align__(16) unsigned char smraw[2 * SM_BUF];
    const uint32_t smbase = (uint32_t)__cvta_generic_to_shared(smraw);

    const int tid  = threadIdx.x;
    const int lane = tid & 31;
    const int wid  = tid >> 5;
    const int warp_m = wid & 1;        // 2
    const int warp_n = wid >> 1;       // 2
    const int m_base = warp_m * 64;
    const int n_base = warp_n * 32;

    const int r8   = (lane & 7) + ((lane >> 3) & 1) * 8;
    const int cadd = lane >> 4;

    float acc[4][4][4];
    #pragma unroll
    for (int i = 0; i < 4; i++)
        #pragma unroll
        for (int nt = 0; nt < 4; nt++)
            #pragma unroll
            for (int q = 0; q < 4; q++) acc[i][nt][q] = 0.f;

    const int cpc = tid & 7;           // chunk 0..7
    const int cpm = tid >> 3;          // base row 0..15

    auto issue_tile = [&](int k0, int buf) {
        uint32_t sb = smbase + buf * SM_BUF;
        #pragma unroll
        for (int h = 0; h < 8; h++) {
            int m = cpm + 16*h;                          // 0..127
            uint32_t d = sb + SM_A + m*128 + ((cpc ^ (m & 7)) << 4);
            const h16* s = (cpc < 4)
                ? (Wh + (size_t)(m0 + m) * K + k0 + cpc*8)
                : (Wl + (size_t)(m0 + m) * K + k0 + (cpc - 4)*8);
            cpa16(d, s);
        }
        #pragma unroll
        for (int h = 0; h < 2; h++) {
            int k = cpm + 16*h;                          // 0..31
            uint32_t d = sb + SM_BH + k*128 + ((cpc ^ (k & 7)) << 4);
            cpa16(d, Xhb + (size_t)(k0 + k) * GN + n0 + cpc*8);
        }
        asm volatile("cp.async.commit_group;" ::: "memory");
    };

    issue_tile(0, 0);
    int cur = 0;
    for (int k0 = 0; k0 < K; k0 += 32) {
        asm volatile("cp.async.wait_group 0;" ::: "memory");
        __syncthreads();
        if (k0 + 32 < K) issue_tile(k0 + 32, cur ^ 1);
        uint32_t sb = smbase + cur * SM_BUF;

        #pragma unroll
        for (int j = 0; j < 2; j++) {                    // two k16 steps
            uint32_t ah[4][4], al[4][4], bh[4][2];
            #pragma unroll
            for (int i = 0; i < 4; i++) {
                int row = m_base + 16*i + r8;
                int ch = 2*j + cadd;
                ldsm4(ah[i], sb + SM_A + row*128 + ((ch ^ (row & 7)) << 4));
                int cl = 4 + 2*j + cadd;
                ldsm4(al[i], sb + SM_A + row*128 + ((cl ^ (row & 7)) << 4));
            }
            #pragma unroll
            for (int u = 0; u < 2; u++) {
                int rowk = 16*j + r8;
                int nc = warp_n*4 + 2*u + cadd;
                uint32_t t[4];
                ldsm4t(t, sb + SM_BH + rowk*128 + ((nc ^ (rowk & 7)) << 4));
                bh[2*u][0] = t[0]; bh[2*u][1] = t[1];
                bh[2*u+1][0] = t[2]; bh[2*u+1][1] = t[3];
            }
            #pragma unroll
            for (int i = 0; i < 4; i++)
                #pragma unroll
                for (int nt = 0; nt < 4; nt++) {
                    mma16816(acc[i][nt], ah[i], bh[nt]);
                    mma16816(acc[i][nt], al[i], bh[nt]);
                }
        }
        cur ^= 1;
    }

    // epilogue
    const int g = lane >> 2, tc = lane & 3;
    #pragma unroll
    for (int i = 0; i < 4; i++) {
        #pragma unroll
        for (int half = 0; half < 2; half++) {
            int row = m0 + m_base + 16*i + g + 8*half;
            float bv = bias ? bias[row] : 0.f;
            size_t rowoff = obase + (size_t)row * GN;
            #pragma unroll
            for (int nt = 0; nt < 4; nt++) {
                int n = n0 + n_base + 8*nt + tc*2;
                float v0 = acc[i][nt][2*half + 0] + bv;
                float v1 = acc[i][nt][2*half + 1] + bv;
                if (ACT == 1) {
                    v0 = 0.5f * v0 * (1.f + erff(v0 * 0.70710678118654752f));
                    v1 = 0.5f * v1 * (1.f + erff(v1 * 0.70710678118654752f));
                }
                if (res) {
                    float2 r = *reinterpret_cast<const float2*>(res + rowoff + n);
                    v0 += r.x; v1 += r.y;
                }
                if (YF) *reinterpret_cast<float2*>(YF + rowoff + n) = make_float2(v0, v1);
                if (YH) {
                    __half2 ph; ph.x = __float2half_rn(v0); ph.y = __float2half_rn(v1);
                    *reinterpret_cast<__half2*>(YH + rowoff + n) = ph;
                }
            }
        }
    }
}

template<int ACT>
static void run_gemm(const h16* Wh, const h16* Wl, const h16* Xh,
                     const float* bias, const float* res,
                     float* YF, h16* YH, int Cout, int K) {
    dim3 g(GN/64, Cout/128, BB), blk(128);
    gemm_f16<ACT><<<g, blk>>>(Wh, Wl, Xh, bias, res, YF, YH, Cout, K);
}

// ---------------- depthwise 3x3 (BN2-folded), writes fp16 ----------------
__global__ __launch_bounds__(256)
void dwconv_kernel(const float* __restrict__ in, h16* __restrict__ oh) {
    int bc = blockIdx.x;          // b*CC + c
    int c  = bc % CC;
    __shared__ float tile[58*58];
    const float* plane = in + (size_t)bc * GN;
    int tid = threadIdx.x;
    for (int idx = tid; idx < 58*58; idx += 256) {
        int ty = idx / 58, tx = idx - ty*58;
        int y = ty - 1, xq = tx - 1;
        float v = 0.f;
        if (y >= 0 && y < 56 && xq >= 0 && xq < 56) v = plane[y*56 + xq];
        tile[idx] = v;
    }
    __syncthreads();
    float w0=g_dwf[c*9+0], w1=g_dwf[c*9+1], w2=g_dwf[c*9+2];
    float w3=g_dwf[c*9+3], w4=g_dwf[c*9+4], w5=g_dwf[c*9+5];
    float w6=g_dwf[c*9+6], w7=g_dwf[c*9+7], w8=g_dwf[c*9+8];
    float bbv = g_dbf[c];
    h16* ohp = oh + (size_t)bc * GN;
    for (int p = tid; p < GN; p += 256) {
        int y = p / 56, xq = p - y*56;
        const float* t = &tile[y*58 + xq];
        float a = bbv + w0*t[0] + w1*t[1] + w2*t[2]
                      + w3*t[58] + w4*t[59] + w5*t[60]
                      + w6*t[116] + w7*t[117] + w8*t[118];
        ohp[p] = __float2half_rn(a);
    }
}

// ---------------- linear attention (fp16 qkv input) ----------------
__device__ __forceinline__ float phi_f(float t) { return expf(0.5f * (2.f*t - t*t)); }

__global__ __launch_bounds__(256)
void attn_kv_kernel(const h16* __restrict__ qkv) {
    int bh = blockIdx.x; int b = bh >> 3, hd = bh & 7;
    int n0 = blockIdx.y * 392;
    __shared__ float kp_s[28*48];
    __shared__ float vv_s[28*48];
    int tid = threadIdx.x;
    int dr[9], er[9];
    #pragma unroll
    for (int r = 0; r < 9; r++) { int de = tid + 256*r; dr[r] = de/48; er[r] = de - dr[r]*48; }
    float acc[9];
    #pragma unroll
    for (int r = 0; r < 9; r++) acc[r] = 0.f;
    float ks = 0.f;
    const h16* kbase = qkv + ((size_t)(b*1152 + CC   + hd*HD)) * GN + n0;
    const h16* vbase = qkv + ((size_t)(b*1152 + 2*CC + hd*HD)) * GN + n0;
    for (int j0 = 0; j0 < 392; j0 += 28) {
        for (int idx = tid; idx < 48*28; idx += 256) {
            int d = idx / 28, j = idx - d*28;
            float kvl = __half2float(kbase[(size_t)d*GN + j0 + j]);
            kp_s[j*48 + d] = phi_f(kvl);
            vv_s[j*48 + d] = __half2float(vbase[(size_t)d*GN + j0 + j]);
        }
        __syncthreads();
        #pragma unroll 4
        for (int j = 0; j < 28; j++) {
            #pragma unroll
            for (int r = 0; r < 9; r++)
                acc[r] = fmaf(kp_s[j*48 + dr[r]], vv_s[j*48 + er[r]], acc[r]);
        }
        if (tid < 48) {
            float s = 0.f;
            #pragma unroll 4
            for (int j = 0; j < 28; j++) s += kp_s[j*48 + tid];
            ks += s;
        }
        __syncthreads();
    }
    #pragma unroll
    for (int r = 0; r < 9; r++) atomicAdd(&g_kv[bh*2304 + tid + 256*r], acc[r]);
    if (tid < 48) atomicAdd(&g_ksum[bh*48 + tid], ks);
}

__global__ __launch_bounds__(256)
void attn_out_kernel(const h16* __restrict__ qkv, h16* __restrict__ oh) {
    int bh = blockIdx.x; int b = bh >> 3, hd = bh & 7;
    int n0 = blockIdx.y * 392;
    __shared__ float kv_s[2304];
    __shared__ float ks_s[48];
    __shared__ float qp_s[28*49];
    __shared__ float dinv[28];
    int tid = threadIdx.x;
    for (int i = tid; i < 2304; i += 256) kv_s[i] = g_kv[bh*2304 + i];
    if (tid < 48) ks_s[tid] = g_ksum[bh*48 + tid];
    __syncthreads();
    const h16* qbase = qkv + ((size_t)(b*1152 + hd*HD)) * GN + n0;
    size_t ob = ((size_t)(b*CC + hd*HD)) * GN + n0;
    for (int j0 = 0; j0 < 392; j0 += 28) {
        for (int idx = tid; idx < 48*28; idx += 256) {
            int d = idx / 28, j = idx - d*28;
            float q = __half2float(qbase[(size_t)d*GN + j0 + j]);
            qp_s[j*49 + d] = phi_f(q);
        }
        __syncthreads();
        if (tid < 28) {
            float s = 0.f;
            #pragma unroll
            for (int d = 0; d < 48; d++) s = fmaf(qp_s[tid*49 + d], ks_s[d], s);
            dinv[tid] = 1.f / (s + 1e-6f);
        }
        __syncthreads();
        for (int idx = tid; idx < 48*28; idx += 256) {
            int e = idx / 28, j = idx - e*28;
            float s = 0.f;
            #pragma unroll
            for (int d = 0; d < 48; d++) s = fmaf(qp_s[j*49 + d], kv_s[d*48 + e], s);
            oh[ob + (size_t)e*GN + j0 + j] = __float2half_rn(s * dinv[j]);
        }
        __syncthreads();
    }
}

// ---------------- LayerNorm over channels, writes fp16 ----------------
__global__ __launch_bounds__(256)
void ln_kernel(const float* __restrict__ x2, const float* __restrict__ lw,
               const float* __restrict__ lb, h16* __restrict__ oh) {
    int b = blockIdx.y; int n0 = blockIdx.x * 16;
    __shared__ float s[CC*17];
    __shared__ float r1[256], r2[256];
    __shared__ float mu[16], ri[16];
    const float* base = x2 + (size_t)b * CC * GN + n0;
    int tid = threadIdx.x;
    for (int idx = tid; idx < CC*16; idx += 256) {
        int c = idx >> 4, j = idx & 15;
        s[c*17 + j] = base[(size_t)c * GN + j];
    }
    __syncthreads();
    {
        int j = tid & 15, part = tid >> 4;
        float sm = 0.f, sq = 0.f;
        for (int c = part*24; c < part*24 + 24; c++) {
            float v = s[c*17 + j]; sm += v; sq = fmaf(v, v, sq);
        }
        r1[tid] = sm; r2[tid] = sq;
    }
    __syncthreads();
    if (tid < 16) {
        float a = 0.f, q = 0.f;
        #pragma unroll
        for (int p = 0; p < 16; p++) { a += r1[p*16 + tid]; q += r2[p*16 + tid]; }
        float mean = a * (1.f/384.f);
        float var = q * (1.f/384.f) - mean*mean;
        mu[tid] = mean; ri[tid] = rsqrtf(var + 1e-5f);
    }
    __syncthreads();
    size_t ob = (size_t)b * CC * GN + n0;
    for (int idx = tid; idx < CC*16; idx += 256) {
        int c = idx >> 4, j = idx & 15;
        float v = (s[c*17 + j] - mu[j]) * ri[j] * lw[c] + lb[c];
        oh[ob + (size_t)c * GN + j] = __float2half_rn(v);
    }
}

// ---------------- launch ----------------
extern "C" void kernel_launch(void* const* d_in, const int* in_sizes, int n_in,
                              void* d_out, int out_size) {
    const float* x      = (const float*)d_in[0];
    const float* bn1_w  = (const float*)d_in[1];
    const float* bn1_b  = (const float*)d_in[2];
    const float* bn1_m  = (const float*)d_in[3];
    const float* bn1_v  = (const float*)d_in[4];
    const float* cw1    = (const float*)d_in[5];
    const float* cb1    = (const float*)d_in[6];
    const float* dw     = (const float*)d_in[7];
    const float* db     = (const float*)d_in[8];
    const float* bn2_w  = (const float*)d_in[9];
    const float* bn2_b  = (const float*)d_in[10];
    const float* bn2_m  = (const float*)d_in[11];
    const float* bn2_v  = (const float*)d_in[12];
    const float* cw2    = (const float*)d_in[13];
    const float* cb2    = (const float*)d_in[14];
    const float* qkv_w  = (const float*)d_in[15];
    const float* proj_w = (const float*)d_in[16];
    const float* proj_b = (const float*)d_in[17];
    const float* ln_w   = (const float*)d_in[18];
    const float* ln_b   = (const float*)d_in[19];
    const float* mlp_w1 = (const float*)d_in[20];
    const float* mlp_b1 = (const float*)d_in[21];
    const float* mlp_w2 = (const float*)d_in[22];
    const float* mlp_b2 = (const float*)d_in[23];

    // symbol addresses
    float *bufA, *x1, *x2, *w1f, *b1f;
    h16 *xh,*dwh,*x1h,*qkvh16,*aoh,*lnh,*hmh;
    h16 *w1fh,*w1fl,*cw2h,*cw2l,*qkvh,*qkvl,*projh,*projl,*w1th,*w1tl,*w2th,*w2tl;
    cudaGetSymbolAddress((void**)&bufA, g_bufA);
    cudaGetSymbolAddress((void**)&x1,   g_x1b);
    cudaGetSymbolAddress((void**)&x2,   g_x2b);
    cudaGetSymbolAddress((void**)&w1f,  g_w1f);
    cudaGetSymbolAddress((void**)&b1f,  g_b1f);
    cudaGetSymbolAddress((void**)&xh,  g_xh);
    cudaGetSymbolAddress((void**)&dwh, g_dwh);
    cudaGetSymbolAddress((void**)&x1h, g_x1h);
    cudaGetSymbolAddress((void**)&qkvh16, g_qkvh16);
    cudaGetSymbolAddress((void**)&aoh, g_aoh);
    cudaGetSymbolAddress((void**)&lnh, g_lnh);
    cudaGetSymbolAddress((void**)&hmh, g_hmh);
    cudaGetSymbolAddress((void**)&w1fh, g_w1fh); cudaGetSymbolAddress((void**)&w1fl, g_w1fl);
    cudaGetSymbolAddress((void**)&cw2h, g_cw2h); cudaGetSymbolAddress((void**)&cw2l, g_cw2l);
    cudaGetSymbolAddress((void**)&qkvh, g_qkvh); cudaGetSymbolAddress((void**)&qkvl, g_qkvl);
    cudaGetSymbolAddress((void**)&projh, g_projh); cudaGetSymbolAddress((void**)&projl, g_projl);
    cudaGetSymbolAddress((void**)&w1th, g_w1th); cudaGetSymbolAddress((void**)&w1tl, g_w1tl);
    cudaGetSymbolAddress((void**)&w2th, g_w2th); cudaGetSymbolAddress((void**)&w2tl, g_w2tl);

    // weight prep
    fold_bn1_kernel<<<CC, 128>>>(cw1, cb1, bn1_w, bn1_b, bn1_m, bn1_v);
    fold_bn2_kernel<<<2, 192>>>(dw, db, bn2_w, bn2_b, bn2_m, bn2_v);
    transpose_split_kernel<<<(CC*4*CC + 255)/256, 256>>>(mlp_w1, w1th, w1tl, CC, 4*CC);
    transpose_split_kernel<<<(CC*4*CC + 255)/256, 256>>>(mlp_w2, w2th, w2tl, 4*CC, CC);
    split_kernel<<<(CC*CC + 255)/256, 256>>>(w1f, w1fh, w1fl, CC*CC);
    split_kernel<<<(CC*CC + 255)/256, 256>>>(cw2, cw2h, cw2l, CC*CC);
    split_kernel<<<(3*CC*CC + 255)/256, 256>>>(qkv_w, qkvh, qkvl, 3*CC*CC);
    split_kernel<<<(CC*CC + 255)/256, 256>>>(proj_w, projh, projl, CC*CC);
    split_kernel<<<(SZ + 255)/256, 256>>>(x, xh, nullptr, SZ);   // hi only
    zero_kv_kernel<<<(BB*NHEADS*HD*HD + 255)/256, 256>>>();

    // conv path
    run_gemm<0>(w1fh, w1fl, xh, b1f, nullptr, bufA, nullptr, CC, CC);
    dwconv_kernel<<<BB*CC, 256>>>(bufA, dwh);
    run_gemm<0>(cw2h, cw2l, dwh, cb2, x, x1, x1h, CC, CC);        // x1 = 1x1 + x (fp32 + fp16)

    // linear attention
    run_gemm<0>(qkvh, qkvl, x1h, nullptr, nullptr, nullptr, qkvh16, 3*CC, CC);  // qkv -> fp16
    attn_kv_kernel<<<dim3(BB*NHEADS, 8), 256>>>(qkvh16);
    attn_out_kernel<<<dim3(BB*NHEADS, 8), 256>>>(qkvh16, aoh);
    run_gemm<0>(projh, projl, aoh, proj_b, x1, x2, nullptr, CC, CC);  // x2 = proj + x1

    // LN + MLP
    ln_kernel<<<dim3(GN/16, BB), 256>>>(x2, ln_w, ln_b, lnh);
    run_gemm<1>(w1th, w1tl, lnh, mlp_b1, nullptr, nullptr, hmh, 4*CC, CC);      // gelu(fc1) -> fp16
    run_gemm<0>(w2th, w2tl, hmh, mlp_b2, x2, (float*)d_out, nullptr, CC, 4*CC); // out = x2 + fc2
}